// round 4
// baseline (speedup 1.0000x reference)
#include <cuda_runtime.h>
#include <cstdint>

// Problem: embedding backward (scatter-add).
//   d_in[0]: grad_output, float32, [B*S, 128]   (B*S = 131072)
//   d_in[1]: indices,     int32 (JAX x64 disabled -> int64 request degrades
//            to int32), [B*S]
//   d_in[2]: num_embeddings (scalar; unused — out covers the full table)
//   d_out  : float32 [num_embeddings, 128]; equals segment_sum with rows
//            where index == 0 (PADDING_IDX) skipped. Padding row stays 0.

static constexpr int D  = 128;     // embedding dim
static constexpr int D4 = D / 4;   // float4s per row = 32 (one warp)

// ---------------------------------------------------------------------------
// Kernel 1: zero the output table with streaming float4 stores.
// ---------------------------------------------------------------------------
__global__ void __launch_bounds__(256) zero_table_kernel(float4* __restrict__ out,
                                                         long long n4) {
    long long i = (long long)blockIdx.x * blockDim.x + threadIdx.x;
    long long stride = (long long)gridDim.x * blockDim.x;
    float4 z = make_float4(0.f, 0.f, 0.f, 0.f);
    for (; i < n4; i += stride) {
        __stcs(&out[i], z);   // streaming store: no read-allocate
    }
}

// ---------------------------------------------------------------------------
// Kernel 2: warp-per-row scatter-add.
//   - lane l owns float4 l of the 128-float row (coalesced 512B/warp read)
//   - uniform per-warp index load (broadcast), whole-warp skip on padding
//   - red.global.add.v4.f32: no-return vector atomic, 4x fewer issue slots
//     than scalar atomicAdd. 16B-aligned by construction.
// ---------------------------------------------------------------------------
__global__ void __launch_bounds__(256) scatter_add_kernel(
    const float4* __restrict__ grad,   // [rows, 32] as float4
    const int* __restrict__ indices,   // [rows], int32
    float* __restrict__ out,           // [V, 128]
    int rows)
{
    int warp = (blockIdx.x * blockDim.x + threadIdx.x) >> 5;
    int lane = threadIdx.x & 31;
    if (warp >= rows) return;

    int e = __ldg(&indices[warp]);
    if (e == 0) return;  // PADDING_IDX — uniform across warp, no divergence

    float4 g = __ldcs(&grad[(long long)warp * D4 + lane]);  // streaming read

    float* dst = out + (long long)e * D + lane * 4;
    asm volatile(
        "red.global.add.v4.f32 [%0], {%1, %2, %3, %4};"
        :
        : "l"(dst), "f"(g.x), "f"(g.y), "f"(g.z), "f"(g.w)
        : "memory");
}

// ---------------------------------------------------------------------------
extern "C" void kernel_launch(void* const* d_in, const int* in_sizes, int n_in,
                              void* d_out, int out_size) {
    const float4* grad   = (const float4*)d_in[0];
    const int* indices   = (const int*)d_in[1];
    float* out           = (float*)d_out;

    const int rows = in_sizes[1];                  // B*S = 131072
    const long long n4 = (long long)out_size / 4;  // float4 count of output

    // Zero the table.
    {
        int threads = 256;
        long long want = (n4 + threads - 1) / threads;
        int blocks = (int)(want < 148 * 32 ? want : 148 * 32);
        if (blocks < 1) blocks = 1;
        zero_table_kernel<<<blocks, threads>>>((float4*)out, n4);
    }

    // Scatter-add: one warp per row.
    {
        int threads = 256;  // 8 warps/CTA
        int warps_per_block = threads / 32;
        int blocks = (rows + warps_per_block - 1) / warps_per_block;
        scatter_add_kernel<<<blocks, threads>>>(grad, indices, out, rows);
    }
}